// round 6
// baseline (speedup 1.0000x reference)
#include <cuda_runtime.h>
#include <cstdint>

namespace {

constexpr int B   = 1024;
constexpr int NP  = 22;
constexpr int DD  = 3;
constexpr int H   = 64;
constexpr int L   = 5;
constexpr int EPB = NP * (NP - 1);   // 462 directed edges per batch
constexpr int HS  = 68;              // h/P/Q/agg stride: 16B-aligned rows
constexpr int MS  = 68;              // m stride: 16B-aligned rows -> LDS/STS.128
constexpr int NT  = 512;             // 16 warps -> 4 warps/SMSP, regs capped at 128

// ---- W_main: one 32KB region overlaid per phase ----
//   P/Q phase : We1[0:128]   (8192 floats)
//   edge phase: We2 [0:4096] + Wc1 [4096:8192]
//   node phase: Wn1 (8192), then Wn2 in [0:4096]
constexpr int WM_SZ = 8192;

// ---- misc small weights (persist through the layer) ----
constexpr int M_WE1R = 0;      // We1 rows 128,129 -> 128 floats
constexpr int M_BE1  = 128;    // 64
constexpr int M_BE2  = 192;    // 64
constexpr int M_BC1  = 256;    // 64
constexpr int M_WATT = 320;    // 64
constexpr int M_WC2  = 384;    // 64
constexpr int M_BN1  = 448;    // 64
constexpr int M_BN2  = 512;    // 64
constexpr int M_BATT = 576;    // 1
constexpr int M_SZ   = 640;

struct __align__(16) Smem {
  float Wm[WM_SZ];            //  32,768 B  phase-overlaid weights
  float misc[M_SZ];           //   2,560 B
  float h[NP * HS];           //   5,984 B
  float P[NP * HS];           //   5,984 B  P_i = h_i @ We1[0:64]
  float Q[NP * HS];           //   5,984 B  Q_i = h_i @ We1[64:128]; reused as node scratch
  float agg[NP * HS];         //   5,984 B
  float m[EPB * MS];          // 125,664 B  m1 then GATED m2 per edge
  float ea[EPB];              //   1,848 B  fixed edge attr (initial sq-dist)
  float trans[EPB * DD];      //   5,544 B
  float coord[NP * DD];       //     264 B
};                            // ~190.6 KB

// ---------------- packed f32x2 helpers ----------------
__device__ __forceinline__ unsigned long long splat2(float v) {
  unsigned long long r;
  unsigned int u = __float_as_uint(v);
  asm("mov.b64 %0, {%1, %1};" : "=l"(r) : "r"(u));
  return r;
}
__device__ __forceinline__ unsigned long long pack2(float a, float b) {
  unsigned long long r;
  asm("mov.b64 %0, {%1, %2};" : "=l"(r) : "r"(__float_as_uint(a)), "r"(__float_as_uint(b)));
  return r;
}
__device__ __forceinline__ unsigned long long ffma2(unsigned long long a,
                                                    unsigned long long b,
                                                    unsigned long long c) {
  unsigned long long d;
  asm("fma.rn.f32x2 %0, %1, %2, %3;" : "=l"(d) : "l"(a), "l"(b), "l"(c));
  return d;
}
__device__ __forceinline__ void unpack2(unsigned long long v, float& lo, float& hi) {
  unsigned int a, b;
  asm("mov.b64 {%0, %1}, %2;" : "=r"(a), "=r"(b) : "l"(v));
  lo = __uint_as_float(a);
  hi = __uint_as_float(b);
}
__device__ __forceinline__ float silu_f(float x) {
  return __fdividef(x, 1.0f + __expf(-x));
}

// full-width (64 outputs) k-step, ONE edge: 16 broadcast LDS.128 -> 32 FFMA2
__device__ __forceinline__ void gfull(unsigned long long acc[32],
                                      const ulonglong2* __restrict__ wrow,
                                      unsigned long long in) {
#pragma unroll
  for (int i = 0; i < 16; i++) {
    ulonglong2 u = wrow[i];
    acc[2 * i]     = ffma2(in, u.x, acc[2 * i]);
    acc[2 * i + 1] = ffma2(in, u.y, acc[2 * i + 1]);
  }
}

__device__ __forceinline__ void cp_f4(float* dst, const float* __restrict__ src,
                                      int nfloats, int tid) {
  float4* d = reinterpret_cast<float4*>(dst);
  const float4* s = reinterpret_cast<const float4*>(src);
  for (int i = tid; i < (nfloats >> 2); i += NT) d[i] = s[i];
}

__global__ void __launch_bounds__(NT, 1)
egnn_kernel(const float* __restrict__ t, const float* __restrict__ x,
            const float* __restrict__ h_init,
            const float* __restrict__ Wemb, const float* __restrict__ bemb,
            const float* __restrict__ We1,  const float* __restrict__ be1,
            const float* __restrict__ We2,  const float* __restrict__ be2,
            const float* __restrict__ Watt, const float* __restrict__ batt,
            const float* __restrict__ Wn1,  const float* __restrict__ bn1,
            const float* __restrict__ Wn2,  const float* __restrict__ bn2,
            const float* __restrict__ Wc1,  const float* __restrict__ bc1,
            const float* __restrict__ Wc2,
            float* __restrict__ out)
{
  extern __shared__ char smem_raw[];
  Smem& s = *reinterpret_cast<Smem*>(smem_raw);
  const int b   = blockIdx.x;
  const int tid = threadIdx.x;
  const int w    = tid >> 5;
  const int lane = tid & 31;

  // ---------- node embedding: h = [one_hot | t] @ Wemb + bemb ----------
  const float tb = t[b];
  for (int task = tid; task < NP * H; task += NT) {
    const int i = task / H, o = task % H;
    float acc = bemb[o] + tb * Wemb[NP * H + o];
#pragma unroll
    for (int j = 0; j < NP; j++) acc += h_init[i * NP + j] * Wemb[j * H + o];
    s.h[i * HS + o] = acc;
  }
  for (int task = tid; task < NP * DD; task += NT)
    s.coord[task] = x[b * (NP * DD) + task];
  __syncthreads();

  // fixed edge attribute from INITIAL coords
  for (int e = tid; e < EPB; e += NT) {
    const int r = e / (NP - 1), jj = e % (NP - 1);
    const int c = jj + (jj >= r ? 1 : 0);
    const float dx = s.coord[r * 3 + 0] - s.coord[c * 3 + 0];
    const float dy = s.coord[r * 3 + 1] - s.coord[c * 3 + 1];
    const float dz = s.coord[r * 3 + 2] - s.coord[c * 3 + 2];
    s.ea[e] = dx * dx + dy * dy + dz * dz;
  }

  for (int l = 0; l < L; l++) {
    // ---------- stage We1[0:128] + misc small weights ----------
    cp_f4(s.Wm, We1 + l * 130 * H, 128 * H, tid);
    cp_f4(s.misc + M_WE1R, We1 + l * 130 * H + 128 * H, 2 * H, tid);
    cp_f4(s.misc + M_BE1,  be1 + l * H, H, tid);
    cp_f4(s.misc + M_BE2,  be2 + l * H, H, tid);
    cp_f4(s.misc + M_BC1,  bc1 + l * H, H, tid);
    cp_f4(s.misc + M_WATT, Watt + l * H, H, tid);
    cp_f4(s.misc + M_WC2,  Wc2 + l * H, H, tid);
    cp_f4(s.misc + M_BN1,  bn1 + l * H, H, tid);
    cp_f4(s.misc + M_BN2,  bn2 + l * H, H, tid);
    if (tid == 0) s.misc[M_BATT] = batt[l];
    __syncthreads();

    // ---------- P/Q phase: warp-per-node (16 warps, 2 rounds) ----------
    {
      const unsigned long long* W1u =
          reinterpret_cast<const unsigned long long*>(s.Wm);  // [128][32 pairs]
#pragma unroll 1
      for (int n = w; n < NP; n += NT / 32) {
        const float* hn = s.h + n * HS;
        unsigned long long accP = 0ull, accQ = 0ull;
#pragma unroll 4
        for (int k = 0; k < H; k++) {
          const unsigned long long hv = splat2(hn[k]);
          accP = ffma2(hv, W1u[k * 32 + lane], accP);
          accQ = ffma2(hv, W1u[(H + k) * 32 + lane], accQ);
        }
        reinterpret_cast<unsigned long long*>(s.P + n * HS)[lane] = accP;
        reinterpret_cast<unsigned long long*>(s.Q + n * HS)[lane] = accQ;
      }
    }
    __syncthreads();

    // ---------- swap weights: We2 -> Wm[0:4096], Wc1 -> Wm[4096:8192] ----------
    cp_f4(s.Wm,        We2 + l * H * H, H * H, tid);
    cp_f4(s.Wm + 4096, Wc1 + l * H * H, H * H, tid);
    __syncthreads();

    // ---------- edge pass: ONE edge per thread (tid < 462) ----------
    if (tid < EPB) {
      const int e = tid;
      const int r = e / (NP - 1), jj = e % (NP - 1);
      const int c = jj + (jj >= r ? 1 : 0);
      const float dx = s.coord[r * 3 + 0] - s.coord[c * 3 + 0];
      const float dy = s.coord[r * 3 + 1] - s.coord[c * 3 + 1];
      const float dz = s.coord[r * 3 + 2] - s.coord[c * 3 + 2];
      const float rad = dx * dx + dy * dy + dz * dz;
      const float eav = s.ea[e];
      float* me = s.m + e * MS;

      // ---- m1 = silu(P_r + Q_c + rad*we1r0 + ea*we1r1 + be1) ----
      {
        const float* Pr = s.P + r * HS;
        const float* Qc = s.Q + c * HS;
        const float* wr = s.misc + M_WE1R;
        const float* we = s.misc + M_WE1R + H;
        const float* bb = s.misc + M_BE1;
#pragma unroll
        for (int o = 0; o < H; o += 4) {
          const float4 p = *reinterpret_cast<const float4*>(Pr + o);
          const float4 q = *reinterpret_cast<const float4*>(Qc + o);
          const float4 wv = *reinterpret_cast<const float4*>(wr + o);
          const float4 ev = *reinterpret_cast<const float4*>(we + o);
          const float4 bv = *reinterpret_cast<const float4*>(bb + o);
          float4 sv;
          sv.x = silu_f(p.x + q.x + rad * wv.x + eav * ev.x + bv.x);
          sv.y = silu_f(p.y + q.y + rad * wv.y + eav * ev.y + bv.y);
          sv.z = silu_f(p.z + q.z + rad * wv.z + eav * ev.z + bv.z);
          sv.w = silu_f(p.w + q.w + rad * wv.w + eav * ev.w + bv.w);
          *reinterpret_cast<float4*>(me + o) = sv;   // STS.128
        }
      }

      unsigned long long acc[32];

      // ---- GEMV2 full-width: m2 = silu(m1 @ We2 + be2); gate; store m2*sg ----
      {
        const unsigned long long* bp =
            reinterpret_cast<const unsigned long long*>(s.misc + M_BE2);
#pragma unroll
        for (int i = 0; i < 32; i++) acc[i] = bp[i];
        const ulonglong2* W2 = reinterpret_cast<const ulonglong2*>(s.Wm);
#pragma unroll 1
        for (int k0 = 0; k0 < H; k0 += 4) {
          const float4 v = *reinterpret_cast<const float4*>(me + k0);  // LDS.128
          gfull(acc, W2 + (k0 + 0) * 16, splat2(v.x));
          gfull(acc, W2 + (k0 + 1) * 16, splat2(v.y));
          gfull(acc, W2 + (k0 + 2) * 16, splat2(v.z));
          gfull(acc, W2 + (k0 + 3) * 16, splat2(v.w));
        }
        float att = s.misc[M_BATT];
#pragma unroll
        for (int i = 0; i < 32; i++) {
          float p, q;
          unpack2(acc[i], p, q);
          p = silu_f(p); q = silu_f(q);
          att += p * s.misc[M_WATT + 2 * i] + q * s.misc[M_WATT + 2 * i + 1];
          acc[i] = pack2(p, q);
        }
        const float sg = __fdividef(1.0f, 1.0f + __expf(-att));
#pragma unroll
        for (int i = 0; i < 16; i++) {
          float p0, q0, p1, q1;
          unpack2(acc[2 * i],     p0, q0);
          unpack2(acc[2 * i + 1], p1, q1);
          *reinterpret_cast<float4*>(me + 4 * i) =
              make_float4(p0 * sg, q0 * sg, p1 * sg, q1 * sg);  // GATED m2
        }
      }

      // ---- GEMVc full-width: phi = silu(m2g @ Wc1 + bc1) . Wc2 ----
      {
        const unsigned long long* bp =
            reinterpret_cast<const unsigned long long*>(s.misc + M_BC1);
#pragma unroll
        for (int i = 0; i < 32; i++) acc[i] = bp[i];
        const ulonglong2* Wc = reinterpret_cast<const ulonglong2*>(s.Wm + 4096);
#pragma unroll 1
        for (int k0 = 0; k0 < H; k0 += 4) {
          const float4 v = *reinterpret_cast<const float4*>(me + k0);  // m2g
          gfull(acc, Wc + (k0 + 0) * 16, splat2(v.x));
          gfull(acc, Wc + (k0 + 1) * 16, splat2(v.y));
          gfull(acc, Wc + (k0 + 2) * 16, splat2(v.z));
          gfull(acc, Wc + (k0 + 3) * 16, splat2(v.w));
        }
        float phi = 0.0f;
#pragma unroll
        for (int i = 0; i < 32; i++) {
          float p, q;
          unpack2(acc[i], p, q);
          phi += silu_f(p) * s.misc[M_WC2 + 2 * i]
               + silu_f(q) * s.misc[M_WC2 + 2 * i + 1];
        }
        const float th = tanhf(phi) * 3.0f;   // COORDS_RANGE
        s.trans[e * 3 + 0] = dx * th;
        s.trans[e * 3 + 1] = dy * th;
        s.trans[e * 3 + 2] = dz * th;
      }
    }
    __syncthreads();

    // ---------- agg (plain sum of gated m2) + coord update; stage Wn1 ----------
    for (int task = tid; task < NP * H; task += NT) {
      const int r = task / H, o = task % H;
      const float* mp = s.m + (r * (NP - 1)) * MS + o;
      float a = 0.0f;
#pragma unroll
      for (int j = 0; j < NP - 1; j++) a += mp[j * MS];
      s.agg[r * HS + o] = a;
    }
    for (int task = tid; task < NP * DD; task += NT) {
      const int r = task / DD, d = task % DD;
      const float* tp = s.trans + (r * (NP - 1)) * DD + d;
      float a = 0.0f;
#pragma unroll
      for (int j = 0; j < NP - 1; j++) a += tp[j * DD];
      s.coord[task] += a;
    }
    cp_f4(s.Wm, Wn1 + l * 128 * H, 128 * H, tid);
    __syncthreads();

    // ---------- node GEMV1: scr(Q) = silu([h | agg] @ Wn1 + bn1) ----------
    {
      const unsigned long long* Wn1u =
          reinterpret_cast<const unsigned long long*>(s.Wm);
      const unsigned long long bn1p =
          reinterpret_cast<const unsigned long long*>(s.misc + M_BN1)[lane];
#pragma unroll 1
      for (int n = w; n < NP; n += NT / 32) {
        const float* hn = s.h + n * HS;
        const float* an = s.agg + n * HS;
        unsigned long long a1 = bn1p;
#pragma unroll 2
        for (int k = 0; k < H; k++) a1 = ffma2(splat2(hn[k]), Wn1u[k * 32 + lane], a1);
#pragma unroll 2
        for (int k = 0; k < H; k++) a1 = ffma2(splat2(an[k]), Wn1u[(H + k) * 32 + lane], a1);
        float lo, hi; unpack2(a1, lo, hi);
        reinterpret_cast<unsigned long long*>(s.Q + n * HS)[lane] =
            pack2(silu_f(lo), silu_f(hi));
      }
    }
    __syncthreads();

    // ---------- swap: Wn2 -> Wm[0:4096] ----------
    cp_f4(s.Wm, Wn2 + l * H * H, H * H, tid);
    __syncthreads();

    // ---------- node GEMV2: h += scr @ Wn2 + bn2 ----------
    {
      const unsigned long long* Wn2u =
          reinterpret_cast<const unsigned long long*>(s.Wm);
      const unsigned long long bn2p =
          reinterpret_cast<const unsigned long long*>(s.misc + M_BN2)[lane];
#pragma unroll 1
      for (int n = w; n < NP; n += NT / 32) {
        const float* sc = s.Q + n * HS;
        unsigned long long a2 = bn2p;
#pragma unroll 2
        for (int k = 0; k < H; k++) a2 = ffma2(splat2(sc[k]), Wn2u[k * 32 + lane], a2);
        float lo, hi; unpack2(a2, lo, hi);
        s.h[n * HS + 2 * lane]     += lo;
        s.h[n * HS + 2 * lane + 1] += hi;
      }
    }
    __syncthreads();
  }

  // ---------- output: vel = (coord - x) - mean_over_particles ----------
  if (tid < DD) {
    float mm = 0.0f;
    for (int i = 0; i < NP; i++)
      mm += s.coord[i * DD + tid] - x[b * (NP * DD) + i * DD + tid];
    s.trans[tid] = mm * (1.0f / NP);
  }
  __syncthreads();
  for (int task = tid; task < NP * DD; task += NT) {
    out[b * (NP * DD) + task] =
        (s.coord[task] - x[b * (NP * DD) + task]) - s.trans[task % DD];
  }
}

}  // namespace

extern "C" void kernel_launch(void* const* d_in, const int* in_sizes, int n_in,
                              void* d_out, int out_size) {
  (void)in_sizes; (void)n_in; (void)out_size;
  const float* t      = (const float*)d_in[0];
  const float* x      = (const float*)d_in[1];
  const float* h_init = (const float*)d_in[2];
  // d_in[3] rows / d_in[4] cols: fixed fully-connected pattern, derived analytically
  const float* Wemb = (const float*)d_in[5];
  const float* bemb = (const float*)d_in[6];
  const float* We1  = (const float*)d_in[7];
  const float* be1  = (const float*)d_in[8];
  const float* We2  = (const float*)d_in[9];
  const float* be2  = (const float*)d_in[10];
  const float* Watt = (const float*)d_in[11];
  const float* batt = (const float*)d_in[12];
  const float* Wn1  = (const float*)d_in[13];
  const float* bn1  = (const float*)d_in[14];
  const float* Wn2  = (const float*)d_in[15];
  const float* bn2  = (const float*)d_in[16];
  const float* Wc1  = (const float*)d_in[17];
  const float* bc1  = (const float*)d_in[18];
  const float* Wc2  = (const float*)d_in[19];

  cudaFuncSetAttribute(egnn_kernel, cudaFuncAttributeMaxDynamicSharedMemorySize,
                       (int)sizeof(Smem));
  egnn_kernel<<<B, NT, sizeof(Smem)>>>(t, x, h_init, Wemb, bemb, We1, be1, We2, be2,
                                       Watt, batt, Wn1, bn1, Wn2, bn2, Wc1, bc1, Wc2,
                                       (float*)d_out);
}